// round 11
// baseline (speedup 1.0000x reference)
#include <cuda_runtime.h>
#include <math.h>

#define CCH   256
#define HFM   50
#define WFM   50
#define HW    (HFM * WFM)
#define POUT  7
#define NS    14            // POUT * sampling_ratio
#define RMAX  4             // max cached region rows/cols (fast path)
#define OUT_PER_ROI (CCH * POUT * POUT)   // 12544 floats

// Transposed feature map scratch: [H][W][C] so channel is contiguous.
__device__ float g_fmT[HW * CCH];

// ---------------------------------------------------------------------------
// Kernel 1: [C][H*W] -> [H*W][C] tiled transpose (2.56 MB, ~1-2 us)
// ---------------------------------------------------------------------------
__global__ void transpose_kernel(const float* __restrict__ fm) {
    __shared__ float tile[32][33];
    const int hw0 = blockIdx.x * 32;
    const int c0  = blockIdx.y * 32;
    const int tx = threadIdx.x, ty = threadIdx.y;   // blockDim = (32, 8)
    #pragma unroll
    for (int i = 0; i < 32; i += 8) {
        const int hw = hw0 + tx;
        float v = 0.0f;
        if (hw < HW) v = fm[(c0 + ty + i) * HW + hw];
        tile[ty + i][tx] = v;
    }
    __syncthreads();
    #pragma unroll
    for (int i = 0; i < 32; i += 8) {
        const int hw = hw0 + ty + i;
        if (hw < HW) g_fmT[hw * CCH + (c0 + tx)] = tile[tx][ty + i];
    }
}

// Reference-exact axis interpolation for sample j of an axis.
__device__ __forceinline__ void axis_sample(float lo, float bin, int L, int j,
                                            int& i0, int& i1, float& h, float& l,
                                            bool& vld) {
    const float v = lo + bin * ((j + 0.5f) * 0.5f);    // grid = (j+0.5)/sr, sr=2
    vld = (v >= -1.0f) && (v <= (float)L);
    const float vc = fminf(fmaxf(v, 0.0f), (float)(L - 1));
    int a = (int)floorf(vc);
    if (a > L - 1) a = L - 1;
    i0 = a;
    i1 = min(a + 1, L - 1);
    l  = vc - (float)a;
    h  = 1.0f - l;
}

// ---------------------------------------------------------------------------
// Kernel 2: one block per ROI, thread = channel.
// Separable aggregated-weight formulation:
//   out[ph][pw] = sum_ry sum_rx AY[ph][ry] * AX[pw][rx] * R[ry][rx]
// Register-lean epilogue: only R[4][4] lives in regs; AX/AY read as
// broadcast LDS. __launch_bounds__(256,4) forces <=64 regs -> 4 CTAs/SM.
// ---------------------------------------------------------------------------
__global__ void __launch_bounds__(256, 4)
roi_kernel(const float* __restrict__ proposals, float* __restrict__ out,
           int nrois) {
    extern __shared__ float sOut[];                 // CCH * 49 floats (49 KB)
    __shared__ float sAX[POUT][RMAX];
    __shared__ float sAY[POUT][RMAX];
    __shared__ int   sMeta[4];                      // ixmin, NC, iymin, NR
    // Raw per-sample data (only needed by the generic fallback path)
    __shared__ int   sI0[2][NS], sI1[2][NS];
    __shared__ float sWH[2][NS], sWL[2][NS];
    __shared__ int   sVd[2][NS];

    const int roi = blockIdx.x;
    const int tid = threadIdx.x;

    // --- Per-ROI weight setup: threads 0..6 handle x (axis 0), 8..14 handle y.
    if (tid < 15 && tid != 7) {
        const int axis = tid >> 3;                  // 0 = x, 1 = y
        const int p    = tid & 7;                   // output bin this thread owns
        const float* b = proposals + (size_t)roi * 4;
        // reference scales twice: proposals * SCALE, then * SCALE inside roi_align
        const float lo = (b[axis]     * (1.0f / 16.0f)) * (1.0f / 16.0f);
        const float hi = (b[axis + 2] * (1.0f / 16.0f)) * (1.0f / 16.0f);
        const float sz  = fmaxf(hi - lo, 1.0f);
        const float bin = sz / 7.0f;
        const int L = axis ? HFM : WFM;

        int a0, a1; float fh, fl; bool vv;
        axis_sample(lo, bin, L, 0, a0, a1, fh, fl, vv);
        const int imin = a0;                        // sample positions monotonic
        axis_sample(lo, bin, L, NS - 1, a0, a1, fh, fl, vv);
        const int imax = a1;
        if (p == 0) {
            sMeta[axis * 2 + 0] = imin;
            sMeta[axis * 2 + 1] = imax - imin + 1;
        }
        float* A = axis ? &sAY[p][0] : &sAX[p][0];
        #pragma unroll
        for (int r = 0; r < RMAX; r++) A[r] = 0.0f;

        #pragma unroll
        for (int t = 0; t < 2; t++) {
            const int j = 2 * p + t;
            int i0, i1; float h, l; bool vld;
            axis_sample(lo, bin, L, j, i0, i1, h, l, vld);
            sI0[axis][j] = i0;  sI1[axis][j] = i1;
            sWH[axis][j] = h;   sWL[axis][j] = l;
            sVd[axis][j] = vld ? 1 : 0;
            if (vld) {
                const int r0 = i0 - imin, r1 = i1 - imin;
                if (r0 < RMAX) A[r0] += 0.5f * h;   // 0.5*0.5 = pool mean 0.25
                if (r1 < RMAX) A[r1] += 0.5f * l;
            }
        }
    }
    __syncthreads();

    const int ixmin = sMeta[0], NC = sMeta[1];
    const int iymin = sMeta[2], NR = sMeta[3];
    const int c = tid;

    if (NR <= RMAX && NC <= RMAX) {
        // ---- Fast path: cached 4x4 region in registers only ----
        float R[RMAX][RMAX];
        #pragma unroll
        for (int ry = 0; ry < RMAX; ry++) {
            const bool rowok = (ry < NR);
            const float* base =
                g_fmT + ((size_t)(iymin + ry) * WFM + ixmin) * CCH + c;
            #pragma unroll
            for (int rx = 0; rx < RMAX; rx++)
                R[ry][rx] = (rowok && rx < NC) ? base[rx * CCH] : 0.0f;
        }
        #pragma unroll
        for (int ph = 0; ph < POUT; ph++) {
            // u[rx] = sum_ry AY[ph][ry] * R[ry][rx]   (broadcast LDS weights)
            float u0 = 0.f, u1 = 0.f, u2 = 0.f, u3 = 0.f;
            #pragma unroll
            for (int ry = 0; ry < RMAX; ry++) {
                const float w = sAY[ph][ry];
                u0 = fmaf(w, R[ry][0], u0);
                u1 = fmaf(w, R[ry][1], u1);
                u2 = fmaf(w, R[ry][2], u2);
                u3 = fmaf(w, R[ry][3], u3);
            }
            #pragma unroll
            for (int pw = 0; pw < POUT; pw++) {
                float o = sAX[pw][0] * u0;
                o = fmaf(sAX[pw][1], u1, o);
                o = fmaf(sAX[pw][2], u2, o);
                o = fmaf(sAX[pw][3], u3, o);
                sOut[c * 49 + ph * POUT + pw] = o;
            }
        }
    } else {
        // ---- Generic fallback (never taken with this data, correctness net)
        for (int s = 0; s < 49; s++) {
            const int ph = s / POUT, pw = s % POUT;
            float acc = 0.0f;
            #pragma unroll
            for (int t = 0; t < 4; t++) {
                const int sy = 2 * ph + (t >> 1);
                const int sx = 2 * pw + (t & 1);
                if (sVd[1][sy] && sVd[0][sx]) {
                    const int y0 = sI0[1][sy], y1 = sI1[1][sy];
                    const int x0 = sI0[0][sx], x1 = sI1[0][sx];
                    const float hy = sWH[1][sy], ly = sWL[1][sy];
                    const float hx = sWH[0][sx], lx = sWL[0][sx];
                    const float* f = g_fmT;
                    float v =
                        hy * (hx * f[((size_t)y0 * WFM + x0) * CCH + c] +
                              lx * f[((size_t)y0 * WFM + x1) * CCH + c]) +
                        ly * (hx * f[((size_t)y1 * WFM + x0) * CCH + c] +
                              lx * f[((size_t)y1 * WFM + x1) * CCH + c]);
                    acc += v;
                }
            }
            sOut[c * 49 + s] = acc * 0.25f;
        }
    }
    __syncthreads();

    // ---- Coalesced float4 flush of the per-ROI tile ----
    float4* o4 = (float4*)(out + (size_t)roi * OUT_PER_ROI);
    const float4* s4 = (const float4*)sOut;
    #pragma unroll 4
    for (int i = tid; i < OUT_PER_ROI / 4; i += 256)
        o4[i] = s4[i];
}

extern "C" void kernel_launch(void* const* d_in, const int* in_sizes, int n_in,
                              void* d_out, int out_size) {
    const float* fm    = (const float*)d_in[0];   // (1,256,50,50) f32
    const float* props = (const float*)d_in[1];   // (1024,4) f32
    float* out = (float*)d_out;                   // (N,256,7,7) f32
    const int nrois = in_sizes[1] / 4;

    // Transpose feature map to [H][W][C]
    dim3 tb(32, 8);
    dim3 tg((HW + 31) / 32, CCH / 32);
    transpose_kernel<<<tg, tb>>>(fm);

    // Main ROI-align kernel: dynamic smem for the 49 KB output staging tile.
    // (cudaFuncSetAttribute is not a stream op -> graph-capture safe.)
    const int smem = OUT_PER_ROI * (int)sizeof(float);   // 50176 B
    cudaFuncSetAttribute(roi_kernel,
                         cudaFuncAttributeMaxDynamicSharedMemorySize, smem);
    roi_kernel<<<nrois, 256, smem>>>(props, out, nrois);
}

// round 16
// speedup vs baseline: 1.1214x; 1.1214x over previous
#include <cuda_runtime.h>
#include <math.h>

#define CCH   256
#define HFM   50
#define WFM   50
#define HW    (HFM * WFM)
#define POUT  7
#define NS    14            // POUT * sampling_ratio
#define RMAX  4             // max cached region rows/cols (fast path)
#define OUT_PER_ROI (CCH * POUT * POUT)   // 12544 floats
#define SLAB  (32 * 49)     // per-CTA staging: 32 channels x 49 outputs

// Transposed feature map scratch: [H][W][C] so channel is contiguous.
__device__ float g_fmT[HW * CCH];

// ---------------------------------------------------------------------------
// Kernel 1: [C][H*W] -> [H*W][C] tiled transpose (2.56 MB, ~1-2 us)
// ---------------------------------------------------------------------------
__global__ void transpose_kernel(const float* __restrict__ fm) {
    __shared__ float tile[32][33];
    const int hw0 = blockIdx.x * 32;
    const int c0  = blockIdx.y * 32;
    const int tx = threadIdx.x, ty = threadIdx.y;   // blockDim = (32, 8)
    #pragma unroll
    for (int i = 0; i < 32; i += 8) {
        const int hw = hw0 + tx;
        float v = 0.0f;
        if (hw < HW) v = fm[(c0 + ty + i) * HW + hw];
        tile[ty + i][tx] = v;
    }
    __syncthreads();
    #pragma unroll
    for (int i = 0; i < 32; i += 8) {
        const int hw = hw0 + ty + i;
        if (hw < HW) g_fmT[hw * CCH + (c0 + tx)] = tile[tx][ty + i];
    }
}

// Reference-exact axis interpolation for sample j of an axis.
__device__ __forceinline__ void axis_sample(float lo, float bin, int L, int j,
                                            int& i0, int& i1, float& h, float& l,
                                            bool& vld) {
    const float v = lo + bin * ((j + 0.5f) * 0.5f);    // grid = (j+0.5)/sr, sr=2
    vld = (v >= -1.0f) && (v <= (float)L);
    const float vc = fminf(fmaxf(v, 0.0f), (float)(L - 1));
    int a = (int)floorf(vc);
    if (a > L - 1) a = L - 1;
    i0 = a;
    i1 = min(a + 1, L - 1);
    l  = vc - (float)a;
    h  = 1.0f - l;
}

// ---------------------------------------------------------------------------
// Kernel 2: ONE WARP PER CTA. blockIdx -> (roi, 32-channel slice).
// No CTA barriers at all: each warp computes its own weights, loads its own
// 4x4xC region, stages its own 32x49 slab, flushes it float4-coalesced.
// 32 CTAs/SM (smem 7KB, regs <=64 via launch_bounds) -> 32 independent
// instruction streams per SM, fully de-correlated stalls.
// ---------------------------------------------------------------------------
__global__ void __launch_bounds__(32, 32)
roi_kernel(const float* __restrict__ proposals, float* __restrict__ out,
           int nrois) {
    __shared__ float sOut[SLAB];                    // 6272 B staging slab
    __shared__ float sAX[POUT][RMAX];
    __shared__ float sAY[POUT][RMAX];
    __shared__ int   sMeta[4];                      // ixmin, NC, iymin, NR
    // Raw per-sample data (only needed by the generic fallback path)
    __shared__ int   sI0[2][NS], sI1[2][NS];
    __shared__ float sWH[2][NS], sWL[2][NS];
    __shared__ int   sVd[2][NS];

    const int roi   = blockIdx.x >> 3;              // 8 slices per ROI
    const int slice = blockIdx.x & 7;
    const int lane  = threadIdx.x;

    // --- Per-ROI weight setup: lanes 0..6 handle x (axis 0), 8..14 handle y.
    if (lane < 15 && lane != 7) {
        const int axis = lane >> 3;                 // 0 = x, 1 = y
        const int p    = lane & 7;                  // output bin this lane owns
        const float* b = proposals + (size_t)roi * 4;
        // reference scales twice: proposals * SCALE, then * SCALE inside roi_align
        const float lo = (b[axis]     * (1.0f / 16.0f)) * (1.0f / 16.0f);
        const float hi = (b[axis + 2] * (1.0f / 16.0f)) * (1.0f / 16.0f);
        const float sz  = fmaxf(hi - lo, 1.0f);
        const float bin = sz / 7.0f;
        const int L = axis ? HFM : WFM;

        int a0, a1; float fh, fl; bool vv;
        axis_sample(lo, bin, L, 0, a0, a1, fh, fl, vv);
        const int imin = a0;                        // sample positions monotonic
        axis_sample(lo, bin, L, NS - 1, a0, a1, fh, fl, vv);
        const int imax = a1;
        if (p == 0) {
            sMeta[axis * 2 + 0] = imin;
            sMeta[axis * 2 + 1] = imax - imin + 1;
        }
        float* A = axis ? &sAY[p][0] : &sAX[p][0];
        #pragma unroll
        for (int r = 0; r < RMAX; r++) A[r] = 0.0f;

        #pragma unroll
        for (int t = 0; t < 2; t++) {
            const int j = 2 * p + t;
            int i0, i1; float h, l; bool vld;
            axis_sample(lo, bin, L, j, i0, i1, h, l, vld);
            sI0[axis][j] = i0;  sI1[axis][j] = i1;
            sWH[axis][j] = h;   sWL[axis][j] = l;
            sVd[axis][j] = vld ? 1 : 0;
            if (vld) {
                const int r0 = i0 - imin, r1 = i1 - imin;
                if (r0 < RMAX) A[r0] += 0.5f * h;   // 0.5*0.5 = pool mean 0.25
                if (r1 < RMAX) A[r1] += 0.5f * l;
            }
        }
    }
    __syncwarp();

    const int ixmin = sMeta[0], NC = sMeta[1];
    const int iymin = sMeta[2], NR = sMeta[3];
    const int c = slice * 32 + lane;                // this lane's channel

    if (NR <= RMAX && NC <= RMAX) {
        // ---- Fast path: cached 4x4 region in registers only ----
        float R[RMAX][RMAX];
        #pragma unroll
        for (int ry = 0; ry < RMAX; ry++) {
            const bool rowok = (ry < NR);
            const float* base =
                g_fmT + ((size_t)(iymin + ry) * WFM + ixmin) * CCH + c;
            #pragma unroll
            for (int rx = 0; rx < RMAX; rx++)
                R[ry][rx] = (rowok && rx < NC) ? base[rx * CCH] : 0.0f;
        }
        #pragma unroll
        for (int ph = 0; ph < POUT; ph++) {
            // u[rx] = sum_ry AY[ph][ry] * R[ry][rx]   (broadcast LDS weights)
            float u0 = 0.f, u1 = 0.f, u2 = 0.f, u3 = 0.f;
            #pragma unroll
            for (int ry = 0; ry < RMAX; ry++) {
                const float w = sAY[ph][ry];
                u0 = fmaf(w, R[ry][0], u0);
                u1 = fmaf(w, R[ry][1], u1);
                u2 = fmaf(w, R[ry][2], u2);
                u3 = fmaf(w, R[ry][3], u3);
            }
            #pragma unroll
            for (int pw = 0; pw < POUT; pw++) {
                float o = sAX[pw][0] * u0;
                o = fmaf(sAX[pw][1], u1, o);
                o = fmaf(sAX[pw][2], u2, o);
                o = fmaf(sAX[pw][3], u3, o);
                sOut[lane * 49 + ph * POUT + pw] = o;
            }
        }
    } else {
        // ---- Generic fallback (never taken with this data, correctness net)
        for (int s = 0; s < 49; s++) {
            const int ph = s / POUT, pw = s % POUT;
            float acc = 0.0f;
            #pragma unroll
            for (int t = 0; t < 4; t++) {
                const int sy = 2 * ph + (t >> 1);
                const int sx = 2 * pw + (t & 1);
                if (sVd[1][sy] && sVd[0][sx]) {
                    const int y0 = sI0[1][sy], y1 = sI1[1][sy];
                    const int x0 = sI0[0][sx], x1 = sI1[0][sx];
                    const float hy = sWH[1][sy], ly = sWL[1][sy];
                    const float hx = sWH[0][sx], lx = sWL[0][sx];
                    const float* f = g_fmT;
                    float v =
                        hy * (hx * f[((size_t)y0 * WFM + x0) * CCH + c] +
                              lx * f[((size_t)y0 * WFM + x1) * CCH + c]) +
                        ly * (hx * f[((size_t)y1 * WFM + x0) * CCH + c] +
                              lx * f[((size_t)y1 * WFM + x1) * CCH + c]);
                    acc += v;
                }
            }
            sOut[lane * 49 + s] = acc * 0.25f;
        }
    }
    __syncwarp();

    // ---- Coalesced float4 flush of this warp's 32x49 slab ----
    // Global offset: roi*12544 + slice*1568  (1568 = 98*16 -> 16B aligned)
    float4* o4 = (float4*)(out + (size_t)roi * OUT_PER_ROI + slice * SLAB);
    const float4* s4 = (const float4*)sOut;
    #pragma unroll 4
    for (int i = lane; i < SLAB / 4; i += 32)       // 392 float4, 12-13 iters
        o4[i] = s4[i];
}

extern "C" void kernel_launch(void* const* d_in, const int* in_sizes, int n_in,
                              void* d_out, int out_size) {
    const float* fm    = (const float*)d_in[0];   // (1,256,50,50) f32
    const float* props = (const float*)d_in[1];   // (1024,4) f32
    float* out = (float*)d_out;                   // (N,256,7,7) f32
    const int nrois = in_sizes[1] / 4;

    // Transpose feature map to [H][W][C]
    dim3 tb(32, 8);
    dim3 tg((HW + 31) / 32, CCH / 32);
    transpose_kernel<<<tg, tb>>>(fm);

    // One warp-CTA per (roi, 32-channel slice): grid = 8*nrois, 32 threads.
    // Static smem only (~7 KB) -> no cudaFuncSetAttribute needed.
    roi_kernel<<<nrois * 8, 32>>>(props, out, nrois);
}